// round 4
// baseline (speedup 1.0000x reference)
#include <cuda_runtime.h>

#define SS 2048
#define DD 64
#define BHN 16
#define BM 64
#define BK 64
#define NT 256
#define SMEM_BYTES ((DD*BM + DD*BK + BK*DD + BK*BM) * 4)  // 64 KB

// ---------- packed f32x2 helpers (sm_100+; ptxas never auto-generates these) ----------
static __device__ __forceinline__ unsigned long long pk2(float lo, float hi) {
    unsigned long long r;
    asm("mov.b64 %0, {%1, %2};" : "=l"(r) : "f"(lo), "f"(hi));
    return r;
}
static __device__ __forceinline__ void upk2(unsigned long long v, float& lo, float& hi) {
    asm("mov.b64 {%0, %1}, %2;" : "=f"(lo), "=f"(hi) : "l"(v));
}
static __device__ __forceinline__ unsigned long long ffma2(unsigned long long a,
                                                           unsigned long long b,
                                                           unsigned long long c) {
    unsigned long long d;
    asm("fma.rn.f32x2 %0, %1, %2, %3;" : "=l"(d) : "l"(a), "l"(b), "l"(c));
    return d;
}

// ============================================================================
// Single fused kernel. Per (64-q tile, bh):
//   s  = Q K^T                      (f32x2, swizzled smem K tile)
//   a  = mask ? -1e9 : s/8
//   e  = exp(a)  -> written to attn_p region (raw, unnormalized)
//   attn_v += a @ V                 (f32x2, via swizzled smem aT)
//   running rowsum L += e           (registers)
// Tail: reduce L over 16 lanes, re-read own e (L2-hot), write p = e/L.
// Softmax without max-subtraction is valid: unmasked logits bounded (|s|/8
// small), masked entries give exp(-1e9) == 0 exactly.
// Thread layout: 256 = 16(tx: k/d groups of 4) x 16(ty: q groups of 4).
// Tiles live in DYNAMIC shared memory (64 KB > 48 KB static limit).
// ============================================================================
__global__ void __launch_bounds__(NT) attn_fused(
    const float* __restrict__ Qg, const float* __restrict__ Kg,
    const float* __restrict__ Vg, const void* __restrict__ Mg,
    float* __restrict__ outV, float* __restrict__ outP, int writeA)
{
    extern __shared__ float smem[];
    float* Qt = smem;                 // [d][q]           16 KB
    float* Kt = Qt + DD * BM;         // [d][k] swizzled  16 KB
    float* Vs = Kt + DD * BK;         // [k][d]           16 KB
    float* aT = Vs + BK * DD;         // [k][q] swizzled  16 KB
    __shared__ int sMaskI32;          // static 4 B (OK alongside dynamic)

    const int tid = threadIdx.x;
    const int tx  = tid & 15;   // 0..15
    const int ty  = tid >> 4;   // 0..15
    const int bh  = blockIdx.y;
    const int q0  = blockIdx.x * BM;

    const float* Qp = Qg + ((size_t)bh * SS + q0) * DD;
    const float* Kp = Kg + (size_t)bh * SS * DD;
    const float* Vp = Vg + (size_t)bh * SS * DD;
    const size_t moff = ((size_t)bh * SS + q0) * (size_t)SS;
    const int* Mp32 = (const int*)Mg + moff;
    const unsigned char* Mp8 = (const unsigned char*)Mg + moff;
    float* Ep = outP + ((size_t)bh * SS + q0) * (size_t)SS;
    float* Vo = outV + ((size_t)bh * SS + q0) * DD;

    // Inline mask-dtype detection on this block's own slice (64 words; a
    // uint8 0/1 buffer read as int words exceeds 1 with prob ~1-2^-60).
    if (tid < 64) {
        unsigned v = (unsigned)Mp32[tid];
        if (__any_sync(0xffffffffu, v > 1u)) { if ((tid & 31) == 0) sMaskI32 = 0; }
        else                                 { if (tid == 0)        sMaskI32 = 1; }
    }
    // (both warps write consistently; value settled by the first __syncthreads)

    // Load Q tile transposed: Qt[d][q]
    for (int i = tid; i < BM * DD / 4; i += NT) {
        int q = i >> 4, d4 = i & 15;
        float4 v = *(const float4*)(Qp + q * DD + d4 * 4);
        Qt[(d4 * 4 + 0) * BM + q] = v.x;
        Qt[(d4 * 4 + 1) * BM + q] = v.y;
        Qt[(d4 * 4 + 2) * BM + q] = v.z;
        Qt[(d4 * 4 + 3) * BM + q] = v.w;
    }

    unsigned long long accv[4][2];
#pragma unroll
    for (int j = 0; j < 4; j++) { accv[j][0] = 0ull; accv[j][1] = 0ull; }
    float L[4] = {0.f, 0.f, 0.f, 0.f};

    for (int kt = 0; kt < SS / BK; kt++) {
        __syncthreads();  // protect smem reuse from previous iteration

        // Fill K tile (transposed, float4-granule XOR swizzle) and V tile.
        for (int i = tid; i < BK * DD / 4; i += NT) {
            int k = i >> 4, d4 = i & 15;
            const float4 kv = *(const float4*)(Kp + (size_t)(kt * BK + k) * DD + d4 * 4);
            int col = (((k >> 2) ^ d4) << 2) + (k & 3);
            Kt[(d4 * 4 + 0) * BK + col] = kv.x;
            Kt[(d4 * 4 + 1) * BK + col] = kv.y;
            Kt[(d4 * 4 + 2) * BK + col] = kv.z;
            Kt[(d4 * 4 + 3) * BK + col] = kv.w;
            const float4 vv4 = *(const float4*)(Vp + (size_t)(kt * BK + k) * DD + d4 * 4);
            *(float4*)(Vs + k * DD + d4 * 4) = vv4;
        }
        __syncthreads();
        const int mI32 = sMaskI32;

        // ---- s = Q K^T  (64-deep inner product over d) ----
        unsigned long long accs[4][2];
#pragma unroll
        for (int j = 0; j < 4; j++) { accs[j][0] = 0ull; accs[j][1] = 0ull; }

#pragma unroll 8
        for (int d = 0; d < DD; d++) {
            unsigned long long ap0 = *(const unsigned long long*)(Qt + d * BM + ty * 4);
            unsigned long long ap1 = *(const unsigned long long*)(Qt + d * BM + ty * 4 + 2);
            float4 b = *(const float4*)(Kt + d * BK + ((tx ^ (d >> 2)) << 2));
            unsigned long long b0 = pk2(b.x, b.x), b1 = pk2(b.y, b.y);
            unsigned long long b2 = pk2(b.z, b.z), b3 = pk2(b.w, b.w);
            accs[0][0] = ffma2(b0, ap0, accs[0][0]); accs[0][1] = ffma2(b0, ap1, accs[0][1]);
            accs[1][0] = ffma2(b1, ap0, accs[1][0]); accs[1][1] = ffma2(b1, ap1, accs[1][1]);
            accs[2][0] = ffma2(b2, ap0, accs[2][0]); accs[2][1] = ffma2(b2, ap1, accs[2][1]);
            accs[3][0] = ffma2(b3, ap0, accs[3][0]); accs[3][1] = ffma2(b3, ap1, accs[3][1]);
        }

        float sv[4][4];  // [j (k offset)][qq]
#pragma unroll
        for (int j = 0; j < 4; j++) {
            upk2(accs[j][0], sv[j][0], sv[j][1]);
            upk2(accs[j][1], sv[j][2], sv[j][3]);
        }

        // ---- mask + scale; write e=exp(a); stage aT (swizzled); rowsum ----
        const int kb = kt * BK + tx * 4;
        const int k0 = tx * 4;
#pragma unroll
        for (int qq = 0; qq < 4; qq++) {
            const int q = ty * 4 + qq;
            int mx, my, mz, mw;
            if (mI32) {
                int4 mi = *(const int4*)(Mp32 + (size_t)q * SS + kb);
                mx = mi.x; my = mi.y; mz = mi.z; mw = mi.w;
            } else {
                uchar4 mu = *(const uchar4*)(Mp8 + (size_t)q * SS + kb);
                mx = mu.x; my = mu.y; mz = mu.z; mw = mu.w;
            }
            float4 w;
            w.x = mx ? -1e9f : sv[0][qq] * 0.125f;
            w.y = my ? -1e9f : sv[1][qq] * 0.125f;
            w.z = mz ? -1e9f : sv[2][qq] * 0.125f;
            w.w = mw ? -1e9f : sv[3][qq] * 0.125f;
            if (writeA) {
                float4 e;
                e.x = mx ? 0.f : __expf(w.x);
                e.y = my ? 0.f : __expf(w.y);
                e.z = mz ? 0.f : __expf(w.z);
                e.w = mw ? 0.f : __expf(w.w);
                L[qq] += (e.x + e.y) + (e.z + e.w);
                *(float4*)(Ep + (size_t)q * SS + kb) = e;
            }
            // aT element (k, q) at pair ((q>>1) ^ (k&31)), elem (q&1)
            aT[(k0 + 0) * BM + (((q >> 1) ^ ((k0 + 0) & 31)) << 1) + (q & 1)] = w.x;
            aT[(k0 + 1) * BM + (((q >> 1) ^ ((k0 + 1) & 31)) << 1) + (q & 1)] = w.y;
            aT[(k0 + 2) * BM + (((q >> 1) ^ ((k0 + 2) & 31)) << 1) + (q & 1)] = w.z;
            aT[(k0 + 3) * BM + (((q >> 1) ^ ((k0 + 3) & 31)) << 1) + (q & 1)] = w.w;
        }
        __syncthreads();

        // ---- attn_v += a @ V  (64-deep inner product over k) ----
#pragma unroll 8
        for (int k = 0; k < BK; k++) {
            unsigned long long a0 =
                *(const unsigned long long*)(aT + k * BM + (((ty * 2 + 0) ^ (k & 31)) << 1));
            unsigned long long a1 =
                *(const unsigned long long*)(aT + k * BM + (((ty * 2 + 1) ^ (k & 31)) << 1));
            float4 b = *(const float4*)(Vs + k * DD + tx * 4);
            unsigned long long b0 = pk2(b.x, b.x), b1 = pk2(b.y, b.y);
            unsigned long long b2 = pk2(b.z, b.z), b3 = pk2(b.w, b.w);
            accv[0][0] = ffma2(b0, a0, accv[0][0]); accv[0][1] = ffma2(b0, a1, accv[0][1]);
            accv[1][0] = ffma2(b1, a0, accv[1][0]); accv[1][1] = ffma2(b1, a1, accv[1][1]);
            accv[2][0] = ffma2(b2, a0, accv[2][0]); accv[2][1] = ffma2(b2, a1, accv[2][1]);
            accv[3][0] = ffma2(b3, a0, accv[3][0]); accv[3][1] = ffma2(b3, a1, accv[3][1]);
        }
    }

    // ---- write attn_v tile ----
    float vv[4][4];  // [j (d offset)][qq]
#pragma unroll
    for (int j = 0; j < 4; j++) {
        upk2(accv[j][0], vv[j][0], vv[j][1]);
        upk2(accv[j][1], vv[j][2], vv[j][3]);
    }
#pragma unroll
    for (int qq = 0; qq < 4; qq++) {
        float4 w = make_float4(vv[0][qq], vv[1][qq], vv[2][qq], vv[3][qq]);
        *(float4*)(Vo + (size_t)(ty * 4 + qq) * DD + tx * 4) = w;
    }

    if (!writeA) return;

    // ---- softmax normalization tail ----
    // Reduce row sums across the 16 tx lanes (a half-warp; same ty group).
#pragma unroll
    for (int o = 1; o < 16; o <<= 1) {
#pragma unroll
        for (int qq = 0; qq < 4; qq++)
            L[qq] += __shfl_xor_sync(0xffffffffu, L[qq], o);
    }
    float inv[4];
#pragma unroll
    for (int qq = 0; qq < 4; qq++) inv[qq] = 1.0f / L[qq];

    // Rescale exactly the elements this thread wrote (own-thread RAW, L2-hot).
#pragma unroll 4
    for (int kt = 0; kt < SS / BK; kt++) {
        const int kb = kt * BK + tx * 4;
#pragma unroll
        for (int qq = 0; qq < 4; qq++) {
            float* p = Ep + (size_t)(ty * 4 + qq) * SS + kb;
            float4 e = *(const float4*)p;
            e.x *= inv[qq]; e.y *= inv[qq]; e.z *= inv[qq]; e.w *= inv[qq];
            *(float4*)p = e;
        }
    }
}

// ============================================================================
extern "C" void kernel_launch(void* const* d_in, const int* in_sizes, int n_in,
                              void* d_out, int out_size)
{
    const float* Q = (const float*)d_in[0];
    const float* K = (const float*)d_in[1];
    const float* V = (const float*)d_in[2];
    const void*  M = d_in[3];

    float* out = (float*)d_out;
    const long long VN = (long long)BHN * SS * DD;            //  2,097,152
    const long long PN = (long long)BHN * SS * (long long)SS; // 67,108,864
    const int writeA = (out_size >= (int)(VN + PN)) ? 1 : 0;

    cudaFuncSetAttribute(attn_fused,
                         cudaFuncAttributeMaxDynamicSharedMemorySize, SMEM_BYTES);

    dim3 g1(SS / BM, BHN);
    attn_fused<<<g1, NT, SMEM_BYTES>>>(Q, K, V, M, out, out + VN, writeA);
}

// round 6
// speedup vs baseline: 1.0191x; 1.0191x over previous
#include <cuda_runtime.h>
#include <cuda_bf16.h>
#include <cstdint>

#define SS 2048
#define DD 64
#define BH 16
#define QT 128          // q rows per block
#define KT 64           // k columns per chunk
#define NCH (SS / KT)   // 32
#define NT 256          // 8 warps
#define SROWB 144       // smem row stride: 72 bf16 = 144 B (conflict-dodging pad)

// dynamic smem byte offsets
#define QH_O 0
#define QL_O 18432
#define KH_O 36864
#define KL_O 46080
#define VH_O 55296
#define VL_O 64512
#define AH_O 73728
#define AL_O 92160
#define SMEM_DYN 110592

// ---------------- legacy-PTX tensor helpers (valid under .target sm_100) ----
static __device__ __forceinline__ void mma_bf16(float* d, uint32_t a0, uint32_t a1,
                                                uint32_t a2, uint32_t a3,
                                                uint32_t b0, uint32_t b1) {
    asm volatile(
        "mma.sync.aligned.m16n8k16.row.col.f32.bf16.bf16.f32 "
        "{%0,%1,%2,%3}, {%4,%5,%6,%7}, {%8,%9}, {%0,%1,%2,%3};"
        : "+f"(d[0]), "+f"(d[1]), "+f"(d[2]), "+f"(d[3])
        : "r"(a0), "r"(a1), "r"(a2), "r"(a3), "r"(b0), "r"(b1));
}
static __device__ __forceinline__ void ldsm_x4(uint32_t& r0, uint32_t& r1,
                                               uint32_t& r2, uint32_t& r3, uint32_t a) {
    asm volatile("ldmatrix.sync.aligned.m8n8.x4.shared.b16 {%0,%1,%2,%3}, [%4];"
                 : "=r"(r0), "=r"(r1), "=r"(r2), "=r"(r3) : "r"(a));
}
static __device__ __forceinline__ void ldsm_x2(uint32_t& r0, uint32_t& r1, uint32_t a) {
    asm volatile("ldmatrix.sync.aligned.m8n8.x2.shared.b16 {%0,%1}, [%2];"
                 : "=r"(r0), "=r"(r1) : "r"(a));
}
static __device__ __forceinline__ void ldsm_x2_t(uint32_t& r0, uint32_t& r1, uint32_t a) {
    asm volatile("ldmatrix.sync.aligned.m8n8.x2.trans.shared.b16 {%0,%1}, [%2];"
                 : "=r"(r0), "=r"(r1) : "r"(a));
}

// split two floats into packed bf16 hi-pair / lo-pair (x -> low 16 bits)
static __device__ __forceinline__ void split2(float x, float y, uint32_t& hp, uint32_t& lp) {
    __nv_bfloat16 hx = __float2bfloat16(x), hy = __float2bfloat16(y);
    __nv_bfloat16 lx = __float2bfloat16(x - __bfloat162float(hx));
    __nv_bfloat16 ly = __float2bfloat16(y - __bfloat162float(hy));
    hp = (uint32_t)__bfloat16_as_ushort(hx) | ((uint32_t)__bfloat16_as_ushort(hy) << 16);
    lp = (uint32_t)__bfloat16_as_ushort(lx) | ((uint32_t)__bfloat16_as_ushort(ly) << 16);
}
static __device__ __forceinline__ float blo(uint32_t p) {
    return __bfloat162float(__ushort_as_bfloat16((unsigned short)(p & 0xffff)));
}
static __device__ __forceinline__ float bhi(uint32_t p) {
    return __bfloat162float(__ushort_as_bfloat16((unsigned short)(p >> 16)));
}

// ============================================================================
__global__ void __launch_bounds__(NT) attn_fused(
    const float* __restrict__ Qg, const float* __restrict__ Kg,
    const float* __restrict__ Vg, const void* __restrict__ Mg,
    float* __restrict__ outV, float* __restrict__ outP)
{
    extern __shared__ char sm[];
    __shared__ int sMaskI32;
    const uint32_t sb = (uint32_t)__cvta_generic_to_shared(sm);

    const int tid = threadIdx.x;
    const int w   = tid >> 5;
    const int lane = tid & 31;
    const int bh = blockIdx.y;
    const int q0 = blockIdx.x * QT;

    const float* Qp = Qg + ((size_t)bh * SS + q0) * DD;
    const float* Kp = Kg + (size_t)bh * SS * DD;
    const float* Vp = Vg + (size_t)bh * SS * DD;
    const size_t moff = ((size_t)bh * SS + q0) * (size_t)SS;
    const int* Mp32 = (const int*)Mg + moff;
    const unsigned char* Mp8 = (const unsigned char*)Mg + moff;
    float* Ep = outP + moff;
    float* Vo = outV + ((size_t)bh * SS + q0) * DD;

    // mask dtype probe (int32 bool-promotion vs raw bytes)
    if (tid < 64) {
        unsigned v = (unsigned)Mp32[tid];
        if (__any_sync(0xffffffffu, v > 1u)) { if ((tid & 31) == 0) sMaskI32 = 0; }
        else                                 { if (tid == 0)        sMaskI32 = 1; }
    }

    // ---- load Q tile -> bf16 hi/lo smem (rows q, 64 cols, stride 72 b16) ----
    {
        const int q = tid >> 1, c0 = (tid & 1) * 32;
        const float* src = Qp + (size_t)q * DD + c0;
        char* dh = sm + QH_O + q * SROWB + c0 * 2;
        char* dl = sm + QL_O + q * SROWB + c0 * 2;
#pragma unroll
        for (int c = 0; c < 32; c += 4) {
            float4 v = *(const float4*)(src + c);
            uint32_t h0, l0, h1, l1;
            split2(v.x, v.y, h0, l0);
            split2(v.z, v.w, h1, l1);
            *(uint32_t*)(dh + c * 2) = h0; *(uint32_t*)(dh + c * 2 + 4) = h1;
            *(uint32_t*)(dl + c * 2) = l0; *(uint32_t*)(dl + c * 2 + 4) = l1;
        }
    }

    float accv[32];
#pragma unroll
    for (int i = 0; i < 32; i++) accv[i] = 0.0f;
    float rs = 0.0f;                       // exp rowsum for row (tid>>1)

    const int fr = lane >> 2;              // frag row 0..7
    const int fc = (lane & 3) * 2;         // frag col (even)

    // precomputed ldmatrix lane addresses (row parts)
    const int aRow   = 16 * w + ((lane >> 3) & 1) * 8 + (lane & 7);   // A frags
    const int aColB  = (lane >> 4) * 8;                               // +ks*16
    const uint32_t qAddr0 = sb + QH_O + aRow * SROWB + aColB * 2;
    const uint32_t aAddr0 = sb + AH_O + aRow * SROWB + aColB * 2;
    const int bRowK  = (lane & 7);                                    // + nt*8
    const int bColK  = ((lane >> 3) & 1) * 8;                         // + ks*16
    const int vRow   = ((lane >> 3) & 1) * 8 + (lane & 7);            // + ks*16

    for (int kt = 0; kt < NCH; kt++) {
        __syncthreads();   // WAR: prev GEMM2 reads vs this chunk's tile writes

        // ---- load K,V chunk [64 seq][64 d] -> hi/lo smem, natural layout ----
        {
            const int k = tid >> 2, d0 = (tid & 3) * 16;
            const float* ks = Kp + (size_t)(kt * KT + k) * DD + d0;
            const float* vs = Vp + (size_t)(kt * KT + k) * DD + d0;
            char* kh = sm + KH_O + k * SROWB + d0 * 2;
            char* kl = sm + KL_O + k * SROWB + d0 * 2;
            char* vh = sm + VH_O + k * SROWB + d0 * 2;
            char* vl = sm + VL_O + k * SROWB + d0 * 2;
#pragma unroll
            for (int c = 0; c < 16; c += 4) {
                float4 a = *(const float4*)(ks + c);
                uint32_t h0, l0, h1, l1;
                split2(a.x, a.y, h0, l0); split2(a.z, a.w, h1, l1);
                *(uint32_t*)(kh + c * 2) = h0; *(uint32_t*)(kh + c * 2 + 4) = h1;
                *(uint32_t*)(kl + c * 2) = l0; *(uint32_t*)(kl + c * 2 + 4) = l1;
                float4 b = *(const float4*)(vs + c);
                split2(b.x, b.y, h0, l0); split2(b.z, b.w, h1, l1);
                *(uint32_t*)(vh + c * 2) = h0; *(uint32_t*)(vh + c * 2 + 4) = h1;
                *(uint32_t*)(vl + c * 2) = l0; *(uint32_t*)(vl + c * 2 + 4) = l1;
            }
        }
        __syncthreads();
        const int mI32 = sMaskI32;

        // ---- GEMM1: S = Q K^T  (3-term bf16) ----
        float sf[8][4];
#pragma unroll
        for (int nt = 0; nt < 8; nt++)
#pragma unroll
            for (int j = 0; j < 4; j++) sf[nt][j] = 0.0f;

#pragma unroll
        for (int ks = 0; ks < 4; ks++) {
            uint32_t ah0, ah1, ah2, ah3, al0, al1, al2, al3;
            ldsm_x4(ah0, ah1, ah2, ah3, qAddr0 + ks * 32);                 // 16 cols*2B
            ldsm_x4(al0, al1, al2, al3, qAddr0 + (QL_O - QH_O) + ks * 32);
#pragma unroll
            for (int nt = 0; nt < 8; nt++) {
                const uint32_t ba = sb + KH_O + (nt * 8 + bRowK) * SROWB + (ks * 16 + bColK) * 2;
                uint32_t bhp0, bhp1, blp0, blp1;
                ldsm_x2(bhp0, bhp1, ba);
                ldsm_x2(blp0, blp1, ba + (KL_O - KH_O));
                mma_bf16(sf[nt], ah0, ah1, ah2, ah3, bhp0, bhp1);
                mma_bf16(sf[nt], ah0, ah1, ah2, ah3, blp0, blp1);
                mma_bf16(sf[nt], al0, al1, al2, al3, bhp0, bhp1);
            }
        }

        // ---- frag epilogue: mask -> a; split -> AH/AL smem ----
        const int q1 = 16 * w + fr, q2 = q1 + 8;
#pragma unroll
        for (int nt = 0; nt < 8; nt++) {
            const int kc = nt * 8 + fc;            // col within chunk (even)
            const int kg = kt * KT + kc;           // global col
            int m0, m1, m2, m3;
            if (mI32) {
                int2 ma = *(const int2*)(Mp32 + (size_t)q1 * SS + kg);
                int2 mb = *(const int2*)(Mp32 + (size_t)q2 * SS + kg);
                m0 = ma.x; m1 = ma.y; m2 = mb.x; m3 = mb.y;
            } else {
                const unsigned char* pa = Mp8 + (size_t)q1 * SS + kg;
                const unsigned char* pb = Mp8 + (size_t)q2 * SS + kg;
                m0 = pa[0]; m1 = pa[1]; m2 = pb[0]; m3 = pb[1];
            }
            float a0 = m0 ? -1e9f : sf[nt][0] * 0.125f;
            float a1 = m1 ? -1e9f : sf[nt][1] * 0.125f;
            float a2 = m2 ? -1e9f : sf[nt][2] * 0.125f;
            float a3 = m3 ? -1e9f : sf[nt][3] * 0.125f;
            uint32_t hp, lp;
            split2(a0, a1, hp, lp);
            *(uint32_t*)(sm + AH_O + q1 * SROWB + kc * 2) = hp;
            *(uint32_t*)(sm + AL_O + q1 * SROWB + kc * 2) = lp;
            split2(a2, a3, hp, lp);
            *(uint32_t*)(sm + AH_O + q2 * SROWB + kc * 2) = hp;
            *(uint32_t*)(sm + AL_O + q2 * SROWB + kc * 2) = lp;
        }
        __syncthreads();

        // ---- exp pass: e = exp(a) -> gmem (raw); rowsum ----
        {
            const int q = tid >> 1, c0 = (tid & 1) * 32;
            const char* ph = sm + AH_O + q * SROWB + c0 * 2;
            const char* pl = sm + AL_O + q * SROWB + c0 * 2;
            float* erow = Ep + (size_t)q * SS + kt * KT + c0;
#pragma unroll
            for (int c = 0; c < 32; c += 2) {
                uint32_t hp = *(const uint32_t*)(ph + c * 2);
                uint32_t lp = *(const uint32_t*)(pl + c * 2);
                float e0 = __expf(blo(hp) + blo(lp));
                float e1 = __expf(bhi(hp) + bhi(lp));
                rs += e0 + e1;
                *(float2*)(erow + c) = make_float2(e0, e1);
            }
        }

        // ---- GEMM2: attn_v += a V  (3-term bf16; V via ldmatrix.trans) ----
#pragma unroll
        for (int ks = 0; ks < 4; ks++) {
            uint32_t ah0, ah1, ah2, ah3, al0, al1, al2, al3;
            ldsm_x4(ah0, ah1, ah2, ah3, aAddr0 + ks * 32);
            ldsm_x4(al0, al1, al2, al3, aAddr0 + (AL_O - AH_O) + ks * 32);
#pragma unroll
            for (int nt = 0; nt < 8; nt++) {
                const uint32_t ba = sb + VH_O + (ks * 16 + vRow) * SROWB + nt * 16;
                uint32_t bhp0, bhp1, blp0, blp1;
                ldsm_x2_t(bhp0, bhp1, ba);
                ldsm_x2_t(blp0, blp1, ba + (VL_O - VH_O));
                mma_bf16(accv + nt * 4, ah0, ah1, ah2, ah3, bhp0, bhp1);
                mma_bf16(accv + nt * 4, ah0, ah1, ah2, ah3, blp0, blp1);
                mma_bf16(accv + nt * 4, al0, al1, al2, al3, bhp0, bhp1);
            }
        }
    }

    // ---- attn_v store ----
    {
        const int q1 = 16 * w + fr, q2 = q1 + 8;
#pragma unroll
        for (int nt = 0; nt < 8; nt++) {
            const int d = nt * 8 + fc;
            *(float2*)(Vo + (size_t)q1 * DD + d) = make_float2(accv[nt * 4 + 0], accv[nt * 4 + 1]);
            *(float2*)(Vo + (size_t)q2 * DD + d) = make_float2(accv[nt * 4 + 2], accv[nt * 4 + 3]);
        }
    }

    // ---- softmax normalization tail ----
    float tot = rs + __shfl_xor_sync(0xffffffffu, rs, 1);
    const float inv = 1.0f / tot;
    __syncthreads();   // all e-writes of this block's rows visible

    {
        const int q = tid >> 1;
        float* row = Ep + (size_t)q * SS + (tid & 1) * 1024;
#pragma unroll 4
        for (int i = 0; i < 256; i++) {
            float4 v = *(const float4*)(row + i * 4);
            v.x *= inv; v.y *= inv; v.z *= inv; v.w *= inv;
            *(float4*)(row + i * 4) = v;
        }
    }
}

// ============================================================================
extern "C" void kernel_launch(void* const* d_in, const int* in_sizes, int n_in,
                              void* d_out, int out_size)
{
    const float* Q = (const float*)d_in[0];
    const float* K = (const float*)d_in[1];
    const float* V = (const float*)d_in[2];
    const void*  M = d_in[3];

    float* out = (float*)d_out;
    const long long VN = (long long)BH * SS * DD;   // attn_v elements
    float* outV = out;
    float* outP = out + VN;                         // attn_p region

    cudaFuncSetAttribute(attn_fused, cudaFuncAttributeMaxDynamicSharedMemorySize, SMEM_DYN);

    dim3 grid(SS / QT, BH);
    attn_fused<<<grid, NT, SMEM_DYN>>>(Q, K, V, M, outV, outP);
}

// round 7
// speedup vs baseline: 1.1275x; 1.1063x over previous
#include <cuda_runtime.h>
#include <cuda_bf16.h>
#include <cstdint>

#define SS 2048
#define DD 64
#define BH 16
#define QT 128          // q rows per block
#define KT 64           // k columns per chunk
#define NCH (SS / KT)   // 32
#define NT 256          // 8 warps
#define SROWB 144       // smem row stride: 72 bf16 = 144 B (conflict-dodging pad)

// dynamic smem byte offsets
#define QH_O 0
#define QL_O 18432
#define KH_O 36864
#define KL_O 46080
#define VH_O 55296
#define VL_O 64512
#define AH_O 73728
#define AL_O 92160
#define SMEM_DYN 110592

// ---------------- legacy-PTX tensor helpers (valid under .target sm_100) ----
static __device__ __forceinline__ void mma_bf16(float* d, uint32_t a0, uint32_t a1,
                                                uint32_t a2, uint32_t a3,
                                                uint32_t b0, uint32_t b1) {
    asm volatile(
        "mma.sync.aligned.m16n8k16.row.col.f32.bf16.bf16.f32 "
        "{%0,%1,%2,%3}, {%4,%5,%6,%7}, {%8,%9}, {%0,%1,%2,%3};"
        : "+f"(d[0]), "+f"(d[1]), "+f"(d[2]), "+f"(d[3])
        : "r"(a0), "r"(a1), "r"(a2), "r"(a3), "r"(b0), "r"(b1));
}
static __device__ __forceinline__ void ldsm_x4(uint32_t& r0, uint32_t& r1,
                                               uint32_t& r2, uint32_t& r3, uint32_t a) {
    asm volatile("ldmatrix.sync.aligned.m8n8.x4.shared.b16 {%0,%1,%2,%3}, [%4];"
                 : "=r"(r0), "=r"(r1), "=r"(r2), "=r"(r3) : "r"(a));
}
static __device__ __forceinline__ void ldsm_x2(uint32_t& r0, uint32_t& r1, uint32_t a) {
    asm volatile("ldmatrix.sync.aligned.m8n8.x2.shared.b16 {%0,%1}, [%2];"
                 : "=r"(r0), "=r"(r1) : "r"(a));
}
static __device__ __forceinline__ void ldsm_x2_t(uint32_t& r0, uint32_t& r1, uint32_t a) {
    asm volatile("ldmatrix.sync.aligned.m8n8.x2.trans.shared.b16 {%0,%1}, [%2];"
                 : "=r"(r0), "=r"(r1) : "r"(a));
}

// split two floats into packed bf16 hi-pair / lo-pair (x -> low 16 bits)
static __device__ __forceinline__ void split2(float x, float y, uint32_t& hp, uint32_t& lp) {
    __nv_bfloat16 hx = __float2bfloat16(x), hy = __float2bfloat16(y);
    __nv_bfloat16 lx = __float2bfloat16(x - __bfloat162float(hx));
    __nv_bfloat16 ly = __float2bfloat16(y - __bfloat162float(hy));
    hp = (uint32_t)__bfloat16_as_ushort(hx) | ((uint32_t)__bfloat16_as_ushort(hy) << 16);
    lp = (uint32_t)__bfloat16_as_ushort(lx) | ((uint32_t)__bfloat16_as_ushort(ly) << 16);
}
static __device__ __forceinline__ float blo(uint32_t p) {
    return __bfloat162float(__ushort_as_bfloat16((unsigned short)(p & 0xffff)));
}
static __device__ __forceinline__ float bhi(uint32_t p) {
    return __bfloat162float(__ushort_as_bfloat16((unsigned short)(p >> 16)));
}

// ============================================================================
// __launch_bounds__(NT, 2): force <=128 regs so TWO CTAs co-reside per SM
// (smem 2x110.6KB fits the 228KB carveout). Cross-CTA overlap hides the
// serialized load->GEMM1->exp->GEMM2 phase latency that capped issue at 13%.
// ============================================================================
__global__ void __launch_bounds__(NT, 2) attn_fused(
    const float* __restrict__ Qg, const float* __restrict__ Kg,
    const float* __restrict__ Vg, const void* __restrict__ Mg,
    float* __restrict__ outV, float* __restrict__ outP)
{
    extern __shared__ char sm[];
    __shared__ int sMaskI32;
    const uint32_t sb = (uint32_t)__cvta_generic_to_shared(sm);

    const int tid = threadIdx.x;
    const int w   = tid >> 5;
    const int lane = tid & 31;
    const int bh = blockIdx.y;
    const int q0 = blockIdx.x * QT;

    const float* Qp = Qg + ((size_t)bh * SS + q0) * DD;
    const float* Kp = Kg + (size_t)bh * SS * DD;
    const float* Vp = Vg + (size_t)bh * SS * DD;
    const size_t moff = ((size_t)bh * SS + q0) * (size_t)SS;
    const int* Mp32 = (const int*)Mg + moff;
    const unsigned char* Mp8 = (const unsigned char*)Mg + moff;
    float* Ep = outP + moff;
    float* Vo = outV + ((size_t)bh * SS + q0) * DD;

    // mask dtype probe (int32 bool-promotion vs raw bytes)
    if (tid < 64) {
        unsigned v = (unsigned)Mp32[tid];
        if (__any_sync(0xffffffffu, v > 1u)) { if ((tid & 31) == 0) sMaskI32 = 0; }
        else                                 { if (tid == 0)        sMaskI32 = 1; }
    }

    // ---- load Q tile -> bf16 hi/lo smem (rows q, 64 cols, stride 72 b16) ----
    {
        const int q = tid >> 1, c0 = (tid & 1) * 32;
        const float* src = Qp + (size_t)q * DD + c0;
        char* dh = sm + QH_O + q * SROWB + c0 * 2;
        char* dl = sm + QL_O + q * SROWB + c0 * 2;
#pragma unroll
        for (int c = 0; c < 32; c += 4) {
            float4 v = *(const float4*)(src + c);
            uint32_t h0, l0, h1, l1;
            split2(v.x, v.y, h0, l0);
            split2(v.z, v.w, h1, l1);
            *(uint32_t*)(dh + c * 2) = h0; *(uint32_t*)(dh + c * 2 + 4) = h1;
            *(uint32_t*)(dl + c * 2) = l0; *(uint32_t*)(dl + c * 2 + 4) = l1;
        }
    }

    float accv[32];
#pragma unroll
    for (int i = 0; i < 32; i++) accv[i] = 0.0f;
    float rs = 0.0f;                       // exp rowsum for row (tid>>1)

    const int fr = lane >> 2;              // frag row 0..7
    const int fc = (lane & 3) * 2;         // frag col (even)

    // precomputed ldmatrix lane addresses (row parts)
    const int aRow   = 16 * w + ((lane >> 3) & 1) * 8 + (lane & 7);   // A frags
    const int aColB  = (lane >> 4) * 8;                               // +ks*16
    const uint32_t qAddr0 = sb + QH_O + aRow * SROWB + aColB * 2;
    const uint32_t aAddr0 = sb + AH_O + aRow * SROWB + aColB * 2;
    const int bRowK  = (lane & 7);                                    // + nt*8
    const int bColK  = ((lane >> 3) & 1) * 8;                         // + ks*16
    const int vRow   = ((lane >> 3) & 1) * 8 + (lane & 7);            // + ks*16

    for (int kt = 0; kt < NCH; kt++) {
        __syncthreads();   // WAR: prev GEMM2 reads vs this chunk's tile writes

        // ---- load K,V chunk [64 seq][64 d] -> hi/lo smem, natural layout ----
        {
            const int k = tid >> 2, d0 = (tid & 3) * 16;
            const float* ks = Kp + (size_t)(kt * KT + k) * DD + d0;
            const float* vs = Vp + (size_t)(kt * KT + k) * DD + d0;
            char* kh = sm + KH_O + k * SROWB + d0 * 2;
            char* kl = sm + KL_O + k * SROWB + d0 * 2;
            char* vh = sm + VH_O + k * SROWB + d0 * 2;
            char* vl = sm + VL_O + k * SROWB + d0 * 2;
#pragma unroll
            for (int c = 0; c < 16; c += 4) {
                float4 a = *(const float4*)(ks + c);
                uint32_t h0, l0, h1, l1;
                split2(a.x, a.y, h0, l0); split2(a.z, a.w, h1, l1);
                *(uint32_t*)(kh + c * 2) = h0; *(uint32_t*)(kh + c * 2 + 4) = h1;
                *(uint32_t*)(kl + c * 2) = l0; *(uint32_t*)(kl + c * 2 + 4) = l1;
                float4 b = *(const float4*)(vs + c);
                split2(b.x, b.y, h0, l0); split2(b.z, b.w, h1, l1);
                *(uint32_t*)(vh + c * 2) = h0; *(uint32_t*)(vh + c * 2 + 4) = h1;
                *(uint32_t*)(vl + c * 2) = l0; *(uint32_t*)(vl + c * 2 + 4) = l1;
            }
        }
        __syncthreads();
        const int mI32 = sMaskI32;

        // ---- GEMM1: S = Q K^T  (3-term bf16) ----
        float sf[8][4];
#pragma unroll
        for (int nt = 0; nt < 8; nt++)
#pragma unroll
            for (int j = 0; j < 4; j++) sf[nt][j] = 0.0f;

#pragma unroll
        for (int ks = 0; ks < 4; ks++) {
            uint32_t ah0, ah1, ah2, ah3, al0, al1, al2, al3;
            ldsm_x4(ah0, ah1, ah2, ah3, qAddr0 + ks * 32);                 // 16 cols*2B
            ldsm_x4(al0, al1, al2, al3, qAddr0 + (QL_O - QH_O) + ks * 32);
#pragma unroll
            for (int nt = 0; nt < 8; nt++) {
                const uint32_t ba = sb + KH_O + (nt * 8 + bRowK) * SROWB + (ks * 16 + bColK) * 2;
                uint32_t bhp0, bhp1, blp0, blp1;
                ldsm_x2(bhp0, bhp1, ba);
                ldsm_x2(blp0, blp1, ba + (KL_O - KH_O));
                mma_bf16(sf[nt], ah0, ah1, ah2, ah3, bhp0, bhp1);
                mma_bf16(sf[nt], ah0, ah1, ah2, ah3, blp0, blp1);
                mma_bf16(sf[nt], al0, al1, al2, al3, bhp0, bhp1);
            }
        }

        // ---- frag epilogue: mask -> a; split -> AH/AL smem ----
        const int q1 = 16 * w + fr, q2 = q1 + 8;
#pragma unroll
        for (int nt = 0; nt < 8; nt++) {
            const int kc = nt * 8 + fc;            // col within chunk (even)
            const int kg = kt * KT + kc;           // global col
            int m0, m1, m2, m3;
            if (mI32) {
                int2 ma = *(const int2*)(Mp32 + (size_t)q1 * SS + kg);
                int2 mb = *(const int2*)(Mp32 + (size_t)q2 * SS + kg);
                m0 = ma.x; m1 = ma.y; m2 = mb.x; m3 = mb.y;
            } else {
                const unsigned char* pa = Mp8 + (size_t)q1 * SS + kg;
                const unsigned char* pb = Mp8 + (size_t)q2 * SS + kg;
                m0 = pa[0]; m1 = pa[1]; m2 = pb[0]; m3 = pb[1];
            }
            float a0 = m0 ? -1e9f : sf[nt][0] * 0.125f;
            float a1 = m1 ? -1e9f : sf[nt][1] * 0.125f;
            float a2 = m2 ? -1e9f : sf[nt][2] * 0.125f;
            float a3 = m3 ? -1e9f : sf[nt][3] * 0.125f;
            uint32_t hp, lp;
            split2(a0, a1, hp, lp);
            *(uint32_t*)(sm + AH_O + q1 * SROWB + kc * 2) = hp;
            *(uint32_t*)(sm + AL_O + q1 * SROWB + kc * 2) = lp;
            split2(a2, a3, hp, lp);
            *(uint32_t*)(sm + AH_O + q2 * SROWB + kc * 2) = hp;
            *(uint32_t*)(sm + AL_O + q2 * SROWB + kc * 2) = lp;
        }
        __syncthreads();

        // ---- exp pass: e = exp(a) -> gmem (raw); rowsum ----
        {
            const int q = tid >> 1, c0 = (tid & 1) * 32;
            const char* ph = sm + AH_O + q * SROWB + c0 * 2;
            const char* pl = sm + AL_O + q * SROWB + c0 * 2;
            float* erow = Ep + (size_t)q * SS + kt * KT + c0;
#pragma unroll
            for (int c = 0; c < 32; c += 2) {
                uint32_t hp = *(const uint32_t*)(ph + c * 2);
                uint32_t lp = *(const uint32_t*)(pl + c * 2);
                float e0 = __expf(blo(hp) + blo(lp));
                float e1 = __expf(bhi(hp) + bhi(lp));
                rs += e0 + e1;
                *(float2*)(erow + c) = make_float2(e0, e1);
            }
        }

        // ---- GEMM2: attn_v += a V  (3-term bf16; V via ldmatrix.trans) ----
#pragma unroll
        for (int ks = 0; ks < 4; ks++) {
            uint32_t ah0, ah1, ah2, ah3, al0, al1, al2, al3;
            ldsm_x4(ah0, ah1, ah2, ah3, aAddr0 + ks * 32);
            ldsm_x4(al0, al1, al2, al3, aAddr0 + (AL_O - AH_O) + ks * 32);
#pragma unroll
            for (int nt = 0; nt < 8; nt++) {
                const uint32_t ba = sb + VH_O + (ks * 16 + vRow) * SROWB + nt * 16;
                uint32_t bhp0, bhp1, blp0, blp1;
                ldsm_x2_t(bhp0, bhp1, ba);
                ldsm_x2_t(blp0, blp1, ba + (VL_O - VH_O));
                mma_bf16(accv + nt * 4, ah0, ah1, ah2, ah3, bhp0, bhp1);
                mma_bf16(accv + nt * 4, ah0, ah1, ah2, ah3, blp0, blp1);
                mma_bf16(accv + nt * 4, al0, al1, al2, al3, bhp0, bhp1);
            }
        }
    }

    // ---- attn_v store ----
    {
        const int q1 = 16 * w + fr, q2 = q1 + 8;
#pragma unroll
        for (int nt = 0; nt < 8; nt++) {
            const int d = nt * 8 + fc;
            *(float2*)(Vo + (size_t)q1 * DD + d) = make_float2(accv[nt * 4 + 0], accv[nt * 4 + 1]);
            *(float2*)(Vo + (size_t)q2 * DD + d) = make_float2(accv[nt * 4 + 2], accv[nt * 4 + 3]);
        }
    }

    // ---- softmax normalization tail ----
    float tot = rs + __shfl_xor_sync(0xffffffffu, rs, 1);
    const float inv = 1.0f / tot;
    __syncthreads();   // all e-writes of this block's rows visible

    {
        const int q = tid >> 1;
        float* row = Ep + (size_t)q * SS + (tid & 1) * 1024;
#pragma unroll 4
        for (int i = 0; i < 256; i++) {
            float4 v = *(const float4*)(row + i * 4);
            v.x *= inv; v.y *= inv; v.z *= inv; v.w *= inv;
            *(float4*)(row + i * 4) = v;
        }
    }
}

// ============================================================================
extern "C" void kernel_launch(void* const* d_in, const int* in_sizes, int n_in,
                              void* d_out, int out_size)
{
    const float* Q = (const float*)d_in[0];
    const float* K = (const float*)d_in[1];
    const float* V = (const float*)d_in[2];
    const void*  M = d_in[3];

    float* out = (float*)d_out;
    const long long VN = (long long)BH * SS * DD;   // attn_v elements
    float* outV = out;
    float* outP = out + VN;                         // attn_p region

    cudaFuncSetAttribute(attn_fused, cudaFuncAttributeMaxDynamicSharedMemorySize, SMEM_DYN);

    dim3 grid(SS / QT, BH);
    attn_fused<<<grid, NT, SMEM_DYN>>>(Q, K, V, M, outV, outP);
}

// round 8
// speedup vs baseline: 1.8039x; 1.6000x over previous
#include <cuda_runtime.h>
#include <cuda_bf16.h>
#include <cstdint>

#define SS 2048
#define DD 64
#define BH 16
#define QT 128          // q rows per block
#define KT 64           // k columns per chunk
#define NCH (SS / KT)   // 32
#define NT 256          // 8 warps
#define SROWB 144       // bf16 tile row stride (72 b16) — conflict-dodging pad
#define EROWF 72        // e-f32 smem row stride in floats (288 B)

// dynamic smem byte offsets
#define QH_O 0
#define QL_O 18432
#define KH_O 36864
#define KL_O 46080
#define VH_O 55296
#define VL_O 64512
#define EF_O 73728      // 128 rows x 288 B = 36864
#define SMEM_DYN 110592

// ---------------- legacy-PTX tensor helpers (valid under .target sm_100) ----
static __device__ __forceinline__ void mma_bf16(float* d, uint32_t a0, uint32_t a1,
                                                uint32_t a2, uint32_t a3,
                                                uint32_t b0, uint32_t b1) {
    asm volatile(
        "mma.sync.aligned.m16n8k16.row.col.f32.bf16.bf16.f32 "
        "{%0,%1,%2,%3}, {%4,%5,%6,%7}, {%8,%9}, {%0,%1,%2,%3};"
        : "+f"(d[0]), "+f"(d[1]), "+f"(d[2]), "+f"(d[3])
        : "r"(a0), "r"(a1), "r"(a2), "r"(a3), "r"(b0), "r"(b1));
}
static __device__ __forceinline__ void ldsm_x4(uint32_t& r0, uint32_t& r1,
                                               uint32_t& r2, uint32_t& r3, uint32_t a) {
    asm volatile("ldmatrix.sync.aligned.m8n8.x4.shared.b16 {%0,%1,%2,%3}, [%4];"
                 : "=r"(r0), "=r"(r1), "=r"(r2), "=r"(r3) : "r"(a));
}
static __device__ __forceinline__ void ldsm_x2(uint32_t& r0, uint32_t& r1, uint32_t a) {
    asm volatile("ldmatrix.sync.aligned.m8n8.x2.shared.b16 {%0,%1}, [%2];"
                 : "=r"(r0), "=r"(r1) : "r"(a));
}
static __device__ __forceinline__ void ldsm_x2_t(uint32_t& r0, uint32_t& r1, uint32_t a) {
    asm volatile("ldmatrix.sync.aligned.m8n8.x2.trans.shared.b16 {%0,%1}, [%2];"
                 : "=r"(r0), "=r"(r1) : "r"(a));
}

// split two floats into packed bf16 hi-pair / lo-pair (x -> low 16 bits)
static __device__ __forceinline__ void split2(float x, float y, uint32_t& hp, uint32_t& lp) {
    __nv_bfloat16 hx = __float2bfloat16(x), hy = __float2bfloat16(y);
    __nv_bfloat16 lx = __float2bfloat16(x - __bfloat162float(hx));
    __nv_bfloat16 ly = __float2bfloat16(y - __bfloat162float(hy));
    hp = (uint32_t)__bfloat16_as_ushort(hx) | ((uint32_t)__bfloat16_as_ushort(hy) << 16);
    lp = (uint32_t)__bfloat16_as_ushort(lx) | ((uint32_t)__bfloat16_as_ushort(ly) << 16);
}

// ============================================================================
__global__ void __launch_bounds__(NT, 2) attn_fused(
    const float* __restrict__ Qg, const float* __restrict__ Kg,
    const float* __restrict__ Vg, const void* __restrict__ Mg,
    float* __restrict__ outV, float* __restrict__ outP)
{
    extern __shared__ char sm[];
    __shared__ int sMaskI32;
    const uint32_t sb = (uint32_t)__cvta_generic_to_shared(sm);

    const int tid = threadIdx.x;
    const int w   = tid >> 5;
    const int lane = tid & 31;
    const int bh = blockIdx.y;
    const int q0 = blockIdx.x * QT;

    const float* Qp = Qg + ((size_t)bh * SS + q0) * DD;
    const float* Kp = Kg + (size_t)bh * SS * DD;
    const float* Vp = Vg + (size_t)bh * SS * DD;
    const size_t moff = ((size_t)bh * SS + q0) * (size_t)SS;
    const int* Mp32 = (const int*)Mg + moff;
    const unsigned char* Mp8 = (const unsigned char*)Mg + moff;
    float* Ep = outP + moff;
    float* Vo = outV + ((size_t)bh * SS + q0) * DD;

    // mask dtype probe (int32 bool-promotion vs raw bytes)
    if (tid < 64) {
        unsigned v = (unsigned)Mp32[tid];
        if (__any_sync(0xffffffffu, v > 1u)) { if ((tid & 31) == 0) sMaskI32 = 0; }
        else                                 { if (tid == 0)        sMaskI32 = 1; }
    }

    // ---- load Q tile -> bf16 hi/lo smem ----
    {
        const int q = tid >> 1, c0 = (tid & 1) * 32;
        const float* src = Qp + (size_t)q * DD + c0;
        char* dh = sm + QH_O + q * SROWB + c0 * 2;
        char* dl = sm + QL_O + q * SROWB + c0 * 2;
#pragma unroll
        for (int c = 0; c < 32; c += 4) {
            float4 v = *(const float4*)(src + c);
            uint32_t h0, l0, h1, l1;
            split2(v.x, v.y, h0, l0);
            split2(v.z, v.w, h1, l1);
            *(uint32_t*)(dh + c * 2) = h0; *(uint32_t*)(dh + c * 2 + 4) = h1;
            *(uint32_t*)(dl + c * 2) = l0; *(uint32_t*)(dl + c * 2 + 4) = l1;
        }
    }

    float accv[32];
#pragma unroll
    for (int i = 0; i < 32; i++) accv[i] = 0.0f;
    float rsAcc = 0.0f;     // lane r (<16) accumulates rowsum of row 16w+r

    const int fr = lane >> 2;              // frag row 0..7
    const int fc = (lane & 3) * 2;         // frag col (even)
    const int q1 = 16 * w + fr, q2 = q1 + 8;

    const int aRow   = 16 * w + ((lane >> 3) & 1) * 8 + (lane & 7);
    const int aColB  = (lane >> 4) * 8;
    const uint32_t qAddr0 = sb + QH_O + aRow * SROWB + aColB * 2;
    const int bRowK  = (lane & 7);
    const int bColK  = ((lane >> 3) & 1) * 8;
    const int vRow   = ((lane >> 3) & 1) * 8 + (lane & 7);

    for (int kt = 0; kt < NCH; kt++) {
        __syncthreads();   // WAR: prev GEMM2 V-reads done before tile overwrite

        // ---- prefetch mask -> 32-bit predicate reg (latency hidden by loads+GEMM1)
        uint32_t mbits = 0;
        if (sMaskI32) {
#pragma unroll
            for (int nt = 0; nt < 8; nt++) {
                const int kg = kt * KT + nt * 8 + fc;
                int2 ma = *(const int2*)(Mp32 + (size_t)q1 * SS + kg);
                int2 mb = *(const int2*)(Mp32 + (size_t)q2 * SS + kg);
                mbits |= ((ma.x ? 1u : 0u) | (ma.y ? 2u : 0u) |
                          (mb.x ? 4u : 0u) | (mb.y ? 8u : 0u)) << (nt * 4);
            }
        } else {
#pragma unroll
            for (int nt = 0; nt < 8; nt++) {
                const int kg = kt * KT + nt * 8 + fc;
                const unsigned char* pa = Mp8 + (size_t)q1 * SS + kg;
                const unsigned char* pb = Mp8 + (size_t)q2 * SS + kg;
                mbits |= ((pa[0] ? 1u : 0u) | (pa[1] ? 2u : 0u) |
                          (pb[0] ? 4u : 0u) | (pb[1] ? 8u : 0u)) << (nt * 4);
            }
        }

        // ---- load K,V chunk [64 seq][64 d] -> hi/lo smem ----
        {
            const int k = tid >> 2, d0 = (tid & 3) * 16;
            const float* ks = Kp + (size_t)(kt * KT + k) * DD + d0;
            const float* vs = Vp + (size_t)(kt * KT + k) * DD + d0;
            char* kh = sm + KH_O + k * SROWB + d0 * 2;
            char* kl = sm + KL_O + k * SROWB + d0 * 2;
            char* vh = sm + VH_O + k * SROWB + d0 * 2;
            char* vl = sm + VL_O + k * SROWB + d0 * 2;
#pragma unroll
            for (int c = 0; c < 16; c += 4) {
                float4 a = *(const float4*)(ks + c);
                uint32_t h0, l0, h1, l1;
                split2(a.x, a.y, h0, l0); split2(a.z, a.w, h1, l1);
                *(uint32_t*)(kh + c * 2) = h0; *(uint32_t*)(kh + c * 2 + 4) = h1;
                *(uint32_t*)(kl + c * 2) = l0; *(uint32_t*)(kl + c * 2 + 4) = l1;
                float4 b = *(const float4*)(vs + c);
                split2(b.x, b.y, h0, l0); split2(b.z, b.w, h1, l1);
                *(uint32_t*)(vh + c * 2) = h0; *(uint32_t*)(vh + c * 2 + 4) = h1;
                *(uint32_t*)(vl + c * 2) = l0; *(uint32_t*)(vl + c * 2 + 4) = l1;
            }
        }
        __syncthreads();

        // ---- GEMM1: S = Q K^T  (3-term bf16) ----
        float sf[8][4];
#pragma unroll
        for (int nt = 0; nt < 8; nt++)
#pragma unroll
            for (int j = 0; j < 4; j++) sf[nt][j] = 0.0f;

#pragma unroll
        for (int ks = 0; ks < 4; ks++) {
            uint32_t ah0, ah1, ah2, ah3, al0, al1, al2, al3;
            ldsm_x4(ah0, ah1, ah2, ah3, qAddr0 + ks * 32);
            ldsm_x4(al0, al1, al2, al3, qAddr0 + (QL_O - QH_O) + ks * 32);
#pragma unroll
            for (int nt = 0; nt < 8; nt++) {
                const uint32_t ba = sb + KH_O + (nt * 8 + bRowK) * SROWB + (ks * 16 + bColK) * 2;
                uint32_t bhp0, bhp1, blp0, blp1;
                ldsm_x2(bhp0, bhp1, ba);
                ldsm_x2(blp0, blp1, ba + (KL_O - KH_O));
                mma_bf16(sf[nt], ah0, ah1, ah2, ah3, bhp0, bhp1);
                mma_bf16(sf[nt], ah0, ah1, ah2, ah3, blp0, blp1);
                mma_bf16(sf[nt], al0, al1, al2, al3, bhp0, bhp1);
            }
        }

        // ---- per k16-slice: mask+scale in regs -> A-frags; e -> smem; GEMM2 ----
#pragma unroll
        for (int ks = 0; ks < 4; ks++) {
            const int n0 = 2 * ks, n1 = 2 * ks + 1;
            const uint32_t mb0 = mbits >> (n0 * 4), mb1 = mbits >> (n1 * 4);
            float a00 = (mb0 & 1) ? -1e9f : sf[n0][0] * 0.125f;
            float a01 = (mb0 & 2) ? -1e9f : sf[n0][1] * 0.125f;
            float a02 = (mb0 & 4) ? -1e9f : sf[n0][2] * 0.125f;
            float a03 = (mb0 & 8) ? -1e9f : sf[n0][3] * 0.125f;
            float a10 = (mb1 & 1) ? -1e9f : sf[n1][0] * 0.125f;
            float a11 = (mb1 & 2) ? -1e9f : sf[n1][1] * 0.125f;
            float a12 = (mb1 & 4) ? -1e9f : sf[n1][2] * 0.125f;
            float a13 = (mb1 & 8) ? -1e9f : sf[n1][3] * 0.125f;

            // e = exp(a) scatter into warp-local smem band (f32)
            {
                const int kc0 = n0 * 8 + fc, kc1 = n1 * 8 + fc;
                float* e1p = (float*)(sm + EF_O) + q1 * EROWF;
                float* e2p = (float*)(sm + EF_O) + q2 * EROWF;
                *(float2*)(e1p + kc0) = make_float2((mb0 & 1) ? 0.f : __expf(a00),
                                                    (mb0 & 2) ? 0.f : __expf(a01));
                *(float2*)(e2p + kc0) = make_float2((mb0 & 4) ? 0.f : __expf(a02),
                                                    (mb0 & 8) ? 0.f : __expf(a03));
                *(float2*)(e1p + kc1) = make_float2((mb1 & 1) ? 0.f : __expf(a10),
                                                    (mb1 & 2) ? 0.f : __expf(a11));
                *(float2*)(e2p + kc1) = make_float2((mb1 & 4) ? 0.f : __expf(a12),
                                                    (mb1 & 8) ? 0.f : __expf(a13));
            }

            // A-fragments for the k16 slice (rows q1/q2, k-cols ks*16 + fc(+8))
            uint32_t r0h, r0l, r1h, r1l, r2h, r2l, r3h, r3l;
            split2(a00, a01, r0h, r0l);
            split2(a02, a03, r1h, r1l);
            split2(a10, a11, r2h, r2l);
            split2(a12, a13, r3h, r3l);

#pragma unroll
            for (int nt = 0; nt < 8; nt++) {
                const uint32_t ba = sb + VH_O + (ks * 16 + vRow) * SROWB + nt * 16;
                uint32_t bhp0, bhp1, blp0, blp1;
                ldsm_x2_t(bhp0, bhp1, ba);
                ldsm_x2_t(blp0, blp1, ba + (VL_O - VH_O));
                mma_bf16(accv + nt * 4, r0h, r1h, r2h, r3h, bhp0, bhp1);
                mma_bf16(accv + nt * 4, r0h, r1h, r2h, r3h, blp0, blp1);
                mma_bf16(accv + nt * 4, r0l, r1l, r2l, r3l, bhp0, bhp1);
            }
        }

        // ---- coalesced e write + rowsum (warp-local band, no CTA sync) ----
        __syncwarp();
#pragma unroll 2
        for (int r = 0; r < 16; r++) {
            const int row = 16 * w + r;
            const float* ep = (const float*)(sm + EF_O) + row * EROWF + lane * 2;
            float2 e = *(const float2*)ep;
            float s = e.x + e.y;
#pragma unroll
            for (int o = 16; o > 0; o >>= 1) s += __shfl_xor_sync(0xffffffffu, s, o);
            rsAcc += (lane == r) ? s : 0.0f;
            *(float2*)(Ep + (size_t)row * SS + kt * KT + lane * 2) = e;
        }
    }

    // ---- attn_v store ----
#pragma unroll
    for (int nt = 0; nt < 8; nt++) {
        const int d = nt * 8 + fc;
        *(float2*)(Vo + (size_t)q1 * DD + d) = make_float2(accv[nt * 4 + 0], accv[nt * 4 + 1]);
        *(float2*)(Vo + (size_t)q2 * DD + d) = make_float2(accv[nt * 4 + 2], accv[nt * 4 + 3]);
    }

    // ---- softmax normalization: warp-per-row, fully coalesced ----
    const float invAcc = 1.0f / rsAcc;     // valid on lanes 0..15
    __syncwarp();                           // all e-stores visible to warp
#pragma unroll 1
    for (int r = 0; r < 16; r++) {
        const float invr = __shfl_sync(0xffffffffu, invAcc, r);
        float* row = Ep + (size_t)(16 * w + r) * SS;
#pragma unroll 4
        for (int i = 0; i < 16; i++) {
            float4 v = *(const float4*)(row + (i * 32 + lane) * 4);
            v.x *= invr; v.y *= invr; v.z *= invr; v.w *= invr;
            *(float4*)(row + (i * 32 + lane) * 4) = v;
        }
    }
}

// ============================================================================
extern "C" void kernel_launch(void* const* d_in, const int* in_sizes, int n_in,
                              void* d_out, int out_size)
{
    const float* Q = (const float*)d_in[0];
    const float* K = (const float*)d_in[1];
    const float* V = (const float*)d_in[2];
    const void*  M = d_in[3];

    float* out = (float*)d_out;
    const long long VN = (long long)BH * SS * DD;   // attn_v elements
    float* outV = out;
    float* outP = out + VN;                         // attn_p region

    cudaFuncSetAttribute(attn_fused, cudaFuncAttributeMaxDynamicSharedMemorySize, SMEM_DYN);

    dim3 grid(SS / QT, BH);
    attn_fused<<<grid, NT, SMEM_DYN>>>(Q, K, V, M, outV, outP);
}

// round 9
// speedup vs baseline: 1.9032x; 1.0551x over previous
#include <cuda_runtime.h>
#include <cuda_bf16.h>
#include <cstdint>

#define SS 2048
#define DD 64
#define BH 16
#define QT 128          // q rows per block
#define KT 64           // k columns per chunk
#define NCH (SS / KT)   // 32
#define NT 256          // 8 warps
#define SROWB 144       // bf16 tile row stride (72 b16) — conflict-dodging pad
#define EROWF 72        // e-f32 smem row stride in floats (288 B)

// dynamic smem byte offsets
#define QH_O 0
#define QL_O 18432
#define KH_O 36864
#define KL_O 46080
#define VH_O 55296
#define VL_O 64512
#define EF_O 73728      // 128 rows x 288 B = 36864
#define SMEM_DYN 110592

// ---------------- legacy-PTX tensor helpers (valid under .target sm_100) ----
static __device__ __forceinline__ void mma_bf16(float* d, uint32_t a0, uint32_t a1,
                                                uint32_t a2, uint32_t a3,
                                                uint32_t b0, uint32_t b1) {
    asm volatile(
        "mma.sync.aligned.m16n8k16.row.col.f32.bf16.bf16.f32 "
        "{%0,%1,%2,%3}, {%4,%5,%6,%7}, {%8,%9}, {%0,%1,%2,%3};"
        : "+f"(d[0]), "+f"(d[1]), "+f"(d[2]), "+f"(d[3])
        : "r"(a0), "r"(a1), "r"(a2), "r"(a3), "r"(b0), "r"(b1));
}
static __device__ __forceinline__ void ldsm_x4(uint32_t& r0, uint32_t& r1,
                                               uint32_t& r2, uint32_t& r3, uint32_t a) {
    asm volatile("ldmatrix.sync.aligned.m8n8.x4.shared.b16 {%0,%1,%2,%3}, [%4];"
                 : "=r"(r0), "=r"(r1), "=r"(r2), "=r"(r3) : "r"(a));
}
static __device__ __forceinline__ void ldsm_x4_t(uint32_t& r0, uint32_t& r1,
                                                 uint32_t& r2, uint32_t& r3, uint32_t a) {
    asm volatile("ldmatrix.sync.aligned.m8n8.x4.trans.shared.b16 {%0,%1,%2,%3}, [%4];"
                 : "=r"(r0), "=r"(r1), "=r"(r2), "=r"(r3) : "r"(a));
}

// split two floats into packed bf16 hi-pair / lo-pair (x -> low 16 bits)
static __device__ __forceinline__ void split2(float x, float y, uint32_t& hp, uint32_t& lp) {
    __nv_bfloat16 hx = __float2bfloat16(x), hy = __float2bfloat16(y);
    __nv_bfloat16 lx = __float2bfloat16(x - __bfloat162float(hx));
    __nv_bfloat16 ly = __float2bfloat16(y - __bfloat162float(hy));
    hp = (uint32_t)__bfloat16_as_ushort(hx) | ((uint32_t)__bfloat16_as_ushort(hy) << 16);
    lp = (uint32_t)__bfloat16_as_ushort(lx) | ((uint32_t)__bfloat16_as_ushort(ly) << 16);
}

// ============================================================================
__global__ void __launch_bounds__(NT, 2) attn_fused(
    const float* __restrict__ Qg, const float* __restrict__ Kg,
    const float* __restrict__ Vg, const void* __restrict__ Mg,
    float* __restrict__ outV, float* __restrict__ outP)
{
    extern __shared__ char sm[];
    __shared__ int sMaskI32;
    const uint32_t sb = (uint32_t)__cvta_generic_to_shared(sm);

    const int tid = threadIdx.x;
    const int w   = tid >> 5;
    const int lane = tid & 31;
    const int bh = blockIdx.y;
    const int q0 = blockIdx.x * QT;

    const float* Qp = Qg + ((size_t)bh * SS + q0) * DD;
    const float* Kp = Kg + (size_t)bh * SS * DD;
    const float* Vp = Vg + (size_t)bh * SS * DD;
    const size_t moff = ((size_t)bh * SS + q0) * (size_t)SS;
    const int* Mp32 = (const int*)Mg + moff;
    const unsigned char* Mp8 = (const unsigned char*)Mg + moff;
    float* Ep = outP + moff;
    float* Vo = outV + ((size_t)bh * SS + q0) * DD;

    // mask dtype probe (int32 bool-promotion vs raw bytes)
    if (tid < 64) {
        unsigned v = (unsigned)Mp32[tid];
        if (__any_sync(0xffffffffu, v > 1u)) { if ((tid & 31) == 0) sMaskI32 = 0; }
        else                                 { if (tid == 0)        sMaskI32 = 1; }
    }

    // ---- load Q tile -> bf16 hi/lo smem ----
    {
        const int q = tid >> 1, c0 = (tid & 1) * 32;
        const float* src = Qp + (size_t)q * DD + c0;
        char* dh = sm + QH_O + q * SROWB + c0 * 2;
        char* dl = sm + QL_O + q * SROWB + c0 * 2;
#pragma unroll
        for (int c = 0; c < 32; c += 4) {
            float4 v = *(const float4*)(src + c);
            uint32_t h0, l0, h1, l1;
            split2(v.x, v.y, h0, l0);
            split2(v.z, v.w, h1, l1);
            *(uint32_t*)(dh + c * 2) = h0; *(uint32_t*)(dh + c * 2 + 4) = h1;
            *(uint32_t*)(dl + c * 2) = l0; *(uint32_t*)(dl + c * 2 + 4) = l1;
        }
    }

    float accv[32];
#pragma unroll
    for (int i = 0; i < 32; i++) accv[i] = 0.0f;
    float rs1 = 0.0f, rs2 = 0.0f;   // this lane's partial rowsums (rows q1/q2)

    const int fr = lane >> 2;              // frag row 0..7
    const int fc = (lane & 3) * 2;         // frag col (even)
    const int q1 = 16 * w + fr, q2 = q1 + 8;

    const int aRow   = 16 * w + ((lane >> 3) & 1) * 8 + (lane & 7);
    const int aColB  = (lane >> 4) * 8;
    const uint32_t qAddr0 = sb + QH_O + aRow * SROWB + aColB * 2;
    // K x4 lane mapping: matrices {ntpair row 0-7 collo, 0-7 colhi, 8-15 collo, 8-15 colhi}
    const int kRow16 = (lane >> 4) * 8 + (lane & 7);
    const int kCol8  = ((lane >> 3) & 1) * 8;
    const uint32_t kAddr0 = sb + KH_O + kRow16 * SROWB + kCol8 * 2;
    // V trans x4 lane mapping: matrices {k 0-7 nt0, k 8-15 nt0, k 0-7 nt1, k 8-15 nt1}
    const int vRow16 = ((lane >> 3) & 1) * 8 + (lane & 7);
    const int vNtSel = lane >> 4;
    const uint32_t vAddr0 = sb + VH_O + vRow16 * SROWB + vNtSel * 16;

    for (int kt = 0; kt < NCH; kt++) {
        __syncthreads();   // WAR: prev GEMM2 V-reads done before tile overwrite

        // ---- prefetch mask -> 32-bit predicate reg ----
        uint32_t mbits = 0;
        if (sMaskI32) {
#pragma unroll
            for (int nt = 0; nt < 8; nt++) {
                const int kg = kt * KT + nt * 8 + fc;
                int2 ma = *(const int2*)(Mp32 + (size_t)q1 * SS + kg);
                int2 mb = *(const int2*)(Mp32 + (size_t)q2 * SS + kg);
                mbits |= ((ma.x ? 1u : 0u) | (ma.y ? 2u : 0u) |
                          (mb.x ? 4u : 0u) | (mb.y ? 8u : 0u)) << (nt * 4);
            }
        } else {
#pragma unroll
            for (int nt = 0; nt < 8; nt++) {
                const int kg = kt * KT + nt * 8 + fc;
                const unsigned char* pa = Mp8 + (size_t)q1 * SS + kg;
                const unsigned char* pb = Mp8 + (size_t)q2 * SS + kg;
                mbits |= ((pa[0] ? 1u : 0u) | (pa[1] ? 2u : 0u) |
                          (pb[0] ? 4u : 0u) | (pb[1] ? 8u : 0u)) << (nt * 4);
            }
        }

        // ---- load K,V chunk [64 seq][64 d] -> hi/lo smem ----
        {
            const int k = tid >> 2, d0 = (tid & 3) * 16;
            const float* ks = Kp + (size_t)(kt * KT + k) * DD + d0;
            const float* vs = Vp + (size_t)(kt * KT + k) * DD + d0;
            char* kh = sm + KH_O + k * SROWB + d0 * 2;
            char* kl = sm + KL_O + k * SROWB + d0 * 2;
            char* vh = sm + VH_O + k * SROWB + d0 * 2;
            char* vl = sm + VL_O + k * SROWB + d0 * 2;
#pragma unroll
            for (int c = 0; c < 16; c += 4) {
                float4 a = *(const float4*)(ks + c);
                uint32_t h0, l0, h1, l1;
                split2(a.x, a.y, h0, l0); split2(a.z, a.w, h1, l1);
                *(uint32_t*)(kh + c * 2) = h0; *(uint32_t*)(kh + c * 2 + 4) = h1;
                *(uint32_t*)(kl + c * 2) = l0; *(uint32_t*)(kl + c * 2 + 4) = l1;
                float4 b = *(const float4*)(vs + c);
                split2(b.x, b.y, h0, l0); split2(b.z, b.w, h1, l1);
                *(uint32_t*)(vh + c * 2) = h0; *(uint32_t*)(vh + c * 2 + 4) = h1;
                *(uint32_t*)(vl + c * 2) = l0; *(uint32_t*)(vl + c * 2 + 4) = l1;
            }
        }
        __syncthreads();

        // ---- GEMM1: S = Q K^T  (3-term bf16, x4 B loads: two nt per ldsm) ----
        float sf[8][4];
#pragma unroll
        for (int nt = 0; nt < 8; nt++)
#pragma unroll
            for (int j = 0; j < 4; j++) sf[nt][j] = 0.0f;

#pragma unroll
        for (int ks = 0; ks < 4; ks++) {
            uint32_t ah0, ah1, ah2, ah3, al0, al1, al2, al3;
            ldsm_x4(ah0, ah1, ah2, ah3, qAddr0 + ks * 32);
            ldsm_x4(al0, al1, al2, al3, qAddr0 + (QL_O - QH_O) + ks * 32);
#pragma unroll
            for (int ntp = 0; ntp < 4; ntp++) {
                const uint32_t ba = kAddr0 + ntp * (16 * SROWB) + ks * 32;
                uint32_t kh0, kh1, kh2, kh3, kl0, kl1, kl2, kl3;
                ldsm_x4(kh0, kh1, kh2, kh3, ba);
                ldsm_x4(kl0, kl1, kl2, kl3, ba + (KL_O - KH_O));
                mma_bf16(sf[2 * ntp],     ah0, ah1, ah2, ah3, kh0, kh1);
                mma_bf16(sf[2 * ntp],     ah0, ah1, ah2, ah3, kl0, kl1);
                mma_bf16(sf[2 * ntp],     al0, al1, al2, al3, kh0, kh1);
                mma_bf16(sf[2 * ntp + 1], ah0, ah1, ah2, ah3, kh2, kh3);
                mma_bf16(sf[2 * ntp + 1], ah0, ah1, ah2, ah3, kl2, kl3);
                mma_bf16(sf[2 * ntp + 1], al0, al1, al2, al3, kh2, kh3);
            }
        }

        // ---- per k16-slice: mask+scale in regs -> A-frags; e -> smem; GEMM2 ----
#pragma unroll
        for (int ks = 0; ks < 4; ks++) {
            const int n0 = 2 * ks, n1 = 2 * ks + 1;
            const uint32_t mb0 = mbits >> (n0 * 4), mb1 = mbits >> (n1 * 4);
            float a00 = (mb0 & 1) ? -1e9f : sf[n0][0] * 0.125f;
            float a01 = (mb0 & 2) ? -1e9f : sf[n0][1] * 0.125f;
            float a02 = (mb0 & 4) ? -1e9f : sf[n0][2] * 0.125f;
            float a03 = (mb0 & 8) ? -1e9f : sf[n0][3] * 0.125f;
            float a10 = (mb1 & 1) ? -1e9f : sf[n1][0] * 0.125f;
            float a11 = (mb1 & 2) ? -1e9f : sf[n1][1] * 0.125f;
            float a12 = (mb1 & 4) ? -1e9f : sf[n1][2] * 0.125f;
            float a13 = (mb1 & 8) ? -1e9f : sf[n1][3] * 0.125f;

            // e = exp(a): accumulate register rowsums, scatter to smem band
            {
                float e00 = (mb0 & 1) ? 0.f : __expf(a00);
                float e01 = (mb0 & 2) ? 0.f : __expf(a01);
                float e02 = (mb0 & 4) ? 0.f : __expf(a02);
                float e03 = (mb0 & 8) ? 0.f : __expf(a03);
                float e10 = (mb1 & 1) ? 0.f : __expf(a10);
                float e11 = (mb1 & 2) ? 0.f : __expf(a11);
                float e12 = (mb1 & 4) ? 0.f : __expf(a12);
                float e13 = (mb1 & 8) ? 0.f : __expf(a13);
                rs1 += (e00 + e01) + (e10 + e11);
                rs2 += (e02 + e03) + (e12 + e13);
                const int kc0 = n0 * 8 + fc, kc1 = n1 * 8 + fc;
                float* e1p = (float*)(sm + EF_O) + q1 * EROWF;
                float* e2p = (float*)(sm + EF_O) + q2 * EROWF;
                *(float2*)(e1p + kc0) = make_float2(e00, e01);
                *(float2*)(e2p + kc0) = make_float2(e02, e03);
                *(float2*)(e1p + kc1) = make_float2(e10, e11);
                *(float2*)(e2p + kc1) = make_float2(e12, e13);
            }

            // A-fragments for the k16 slice
            uint32_t r0h, r0l, r1h, r1l, r2h, r2l, r3h, r3l;
            split2(a00, a01, r0h, r0l);
            split2(a02, a03, r1h, r1l);
            split2(a10, a11, r2h, r2l);
            split2(a12, a13, r3h, r3l);

#pragma unroll
            for (int ntp = 0; ntp < 4; ntp++) {
                const uint32_t ba = vAddr0 + (ks * 16) * SROWB + ntp * 32;
                uint32_t vh0, vh1, vh2, vh3, vl0, vl1, vl2, vl3;
                ldsm_x4_t(vh0, vh1, vh2, vh3, ba);
                ldsm_x4_t(vl0, vl1, vl2, vl3, ba + (VL_O - VH_O));
                float* d0 = accv + (2 * ntp) * 4;
                float* d1 = accv + (2 * ntp + 1) * 4;
                mma_bf16(d0, r0h, r1h, r2h, r3h, vh0, vh1);
                mma_bf16(d0, r0h, r1h, r2h, r3h, vl0, vl1);
                mma_bf16(d0, r0l, r1l, r2l, r3l, vh0, vh1);
                mma_bf16(d1, r0h, r1h, r2h, r3h, vh2, vh3);
                mma_bf16(d1, r0h, r1h, r2h, r3h, vl2, vl3);
                mma_bf16(d1, r0l, r1l, r2l, r3l, vh2, vh3);
            }
        }

        // ---- coalesced e write (warp-local band; two rows per iteration) ----
        __syncwarp();
        {
            const int half = lane >> 4;       // 0,1
            const int l16  = lane & 15;
#pragma unroll
            for (int rr = 0; rr < 16; rr += 2) {
                const int row = 16 * w + rr + half;
                const float* ep = (const float*)(sm + EF_O) + row * EROWF + l16 * 4;
                float4 e = *(const float4*)ep;
                *(float4*)(Ep + (size_t)row * SS + kt * KT + l16 * 4) = e;
            }
        }
        __syncwarp();   // reads done before next chunk's scatter
    }

    // ---- attn_v store ----
#pragma unroll
    for (int nt = 0; nt < 8; nt++) {
        const int d = nt * 8 + fc;
        *(float2*)(Vo + (size_t)q1 * DD + d) = make_float2(accv[nt * 4 + 0], accv[nt * 4 + 1]);
        *(float2*)(Vo + (size_t)q2 * DD + d) = make_float2(accv[nt * 4 + 2], accv[nt * 4 + 3]);
    }

    // ---- rowsum quad-reduce: lane 4r -> rows 16w+r (rs1), 16w+8+r (rs2) ----
    rs1 += __shfl_xor_sync(0xffffffffu, rs1, 1);
    rs1 += __shfl_xor_sync(0xffffffffu, rs1, 2);
    rs2 += __shfl_xor_sync(0xffffffffu, rs2, 1);
    rs2 += __shfl_xor_sync(0xffffffffu, rs2, 2);

    // ---- softmax normalization: warp-per-row, coalesced, last-written-first ----
#pragma unroll 1
    for (int r = 15; r >= 0; r--) {
        const float s1 = __shfl_sync(0xffffffffu, rs1, (r & 7) * 4);
        const float s2 = __shfl_sync(0xffffffffu, rs2, (r & 7) * 4);
        const float invr = 1.0f / (r < 8 ? s1 : s2);
        float* row = Ep + (size_t)(16 * w + r) * SS;
#pragma unroll 4
        for (int i = 15; i >= 0; i--) {
            float4 v = *(const float4*)(row + (i * 32 + lane) * 4);
            v.x *= invr; v.y *= invr; v.z *= invr; v.w *= invr;
            *(float4*)(row + (i * 32 + lane) * 4) = v;
        }
    }
}

// ============================================================================
extern "C" void kernel_launch(void* const* d_in, const int* in_sizes, int n_in,
                              void* d_out, int out_size)
{
    const float* Q = (const float*)d_in[0];
    const float* K = (const float*)d_in[1];
    const float* V = (const float*)d_in[2];
    const void*  M = d_in[3];

    float* out = (float*)d_out;
    const long long VN = (long long)BH * SS * DD;   // attn_v elements
    float* outV = out;
    float* outP = out + VN;                         // attn_p region

    cudaFuncSetAttribute(attn_fused, cudaFuncAttributeMaxDynamicSharedMemorySize, SMEM_DYN);

    dim3 grid(SS / QT, BH);
    attn_fused<<<grid, NT, SMEM_DYN>>>(Q, K, V, M, outV, outP);
}